// round 10
// baseline (speedup 1.0000x reference)
#include <cuda_runtime.h>
#include <cuda_bf16.h>
#include <cstdint>

#define B 2
#define S 2048
#define HIDDEN 896
#define NH 14
#define NKV 2
#define HD 64
#define NREP 7
#define MTOK (B*S)          // 4096 tokens

// element counts (float4 units)
#define NX4  (MTOK*HIDDEN/4)        // 917504
#define NQ4  (HIDDEN*HIDDEN/4)      // 200704
#define NK4  (NKV*HD*HIDDEN/4)      // 28672
#define NV4  NK4
#define NO4  NQ4
#define TOT4 (NX4 + NQ4 + NK4 + NV4 + NO4)   // 1376256

// ---------------- scratch (device globals) ----------------
__device__ float g_q[B * NH * S * HD];         // [b,h,s,d]  (pre-scaled, tf32-rounded)
__device__ float g_k[B * NKV * S * HD];        // [b,kv,s,d] (tf32-rounded)
__device__ float g_vt[B * NKV * HD * S];       // [b,kv,d,s] TRANSPOSED (tf32-rounded)
__device__ float2 g_rope[S * 32];

// bf16 hi/lo pre-converted operands (uint2 = 4 bf16)
__device__ uint2 g_xhi[NX4],  g_xlo[NX4];      // hidden_states
__device__ uint2 g_wqhi[NQ4], g_wqlo[NQ4];
__device__ uint2 g_wkhi[NK4], g_wklo[NK4];
__device__ uint2 g_wvhi[NV4], g_wvlo[NV4];
__device__ uint2 g_wohi[NO4], g_wolo[NO4];
__device__ uint2 g_ahi[NX4],  g_alo[NX4];      // attention output

// Q pre-scale: 1/sqrt(64) * log2(e)
#define ASCALE 0.1803368801111204f

// ---------------- helpers ----------------
__device__ __forceinline__ uint32_t f2tf32(float x) {
    uint32_t r;
    asm("cvt.rna.tf32.f32 %0, %1;" : "=r"(r) : "f"(x));
    return r;
}

__device__ __forceinline__ void mma_tf32(float* d, const uint32_t* a, uint32_t b0, uint32_t b1) {
    asm volatile(
        "mma.sync.aligned.m16n8k8.row.col.f32.tf32.tf32.f32 "
        "{%0,%1,%2,%3}, {%4,%5,%6,%7}, {%8,%9}, {%0,%1,%2,%3};\n"
        : "+f"(d[0]), "+f"(d[1]), "+f"(d[2]), "+f"(d[3])
        : "r"(a[0]), "r"(a[1]), "r"(a[2]), "r"(a[3]), "r"(b0), "r"(b1));
}

__device__ __forceinline__ void mma_bf16(float* d, const uint32_t* a, uint32_t b0, uint32_t b1) {
    asm volatile(
        "mma.sync.aligned.m16n8k16.row.col.f32.bf16.bf16.f32 "
        "{%0,%1,%2,%3}, {%4,%5,%6,%7}, {%8,%9}, {%0,%1,%2,%3};\n"
        : "+f"(d[0]), "+f"(d[1]), "+f"(d[2]), "+f"(d[3])
        : "r"(a[0]), "r"(a[1]), "r"(a[2]), "r"(a[3]), "r"(b0), "r"(b1));
}

#define LDSM_X4(r0, r1, r2, r3, addr) \
    asm volatile("ldmatrix.sync.aligned.m8n8.x4.shared.b16 {%0,%1,%2,%3}, [%4];" \
                 : "=r"(r0), "=r"(r1), "=r"(r2), "=r"(r3) : "r"(addr))

#define CP_ASYNC16(dst, src) \
    asm volatile("cp.async.ca.shared.global [%0], [%1], 16;" :: "r"(dst), "l"(src))
#define CP_COMMIT() asm volatile("cp.async.commit_group;" ::: "memory")
#define CP_WAIT(n)  asm volatile("cp.async.wait_group %0;" :: "n"(n) : "memory")

// pack two floats into bf16x2 hi word + bf16x2 lo (residual) word
__device__ __forceinline__ void split2(float x0, float x1, uint32_t& hi, uint32_t& lo) {
    asm("cvt.rn.bf16x2.f32 %0, %1, %2;" : "=r"(hi) : "f"(x1), "f"(x0));
    float h0 = __uint_as_float(hi << 16);
    float h1 = __uint_as_float(hi & 0xffff0000u);
    float r0 = x0 - h0;
    float r1 = x1 - h1;
    asm("cvt.rn.bf16x2.f32 %0, %1, %2;" : "=r"(lo) : "f"(r1), "f"(r0));
}

// ---------------- conversion pass: fp32 -> bf16 hi/lo ----------------
__global__ void conv_split(const float4* __restrict__ x,
                           const float4* __restrict__ wq,
                           const float4* __restrict__ wk,
                           const float4* __restrict__ wv,
                           const float4* __restrict__ wo) {
    int i = blockIdx.x * blockDim.x + threadIdx.x;
    if (i >= TOT4) return;
    const float4* src;
    uint2 *hi, *lo;
    int off = i;
    if (off < NX4)                    { src = x;  hi = g_xhi;  lo = g_xlo; }
    else if ((off -= NX4) < NQ4)      { src = wq; hi = g_wqhi; lo = g_wqlo; }
    else if ((off -= NQ4) < NK4)      { src = wk; hi = g_wkhi; lo = g_wklo; }
    else if ((off -= NK4) < NV4)      { src = wv; hi = g_wvhi; lo = g_wvlo; }
    else { off -= NV4;                  src = wo; hi = g_wohi; lo = g_wolo; }
    float4 v = src[off];
    uint2 h, l;
    split2(v.x, v.y, h.x, l.x);
    split2(v.z, v.w, h.y, l.y);
    hi[off] = h;
    lo[off] = l;
}

// ---------------- rope table ----------------
__global__ void build_rope(float2* tab) {
    int idx = blockIdx.x * blockDim.x + threadIdx.x;   // [0, S*32)
    int s = idx >> 5, i = idx & 31;
    const float LOG2_THETA_OVER_32 = 0.62286105580517513f;  // log2(1e6)/32
    float inv = exp2f(-(float)i * LOG2_THETA_OVER_32);
    float sn, cs;
    sincosf((float)s * inv, &sn, &cs);
    tab[idx] = make_float2(cs, sn);
}

// ---------------- GEMM core: pre-split bf16, CTA 128x64, 128 thr, BK=32 ----------
#define XH_OFF 0
#define XL_OFF 10240
#define WH_OFF 20480
#define WL_OFF 25600
#define GBUF   30720
#define GEMM_SMEM (2 * GBUF)
#define NKCH (HIDDEN / 32)     // 28

__device__ __forceinline__ void gemm3_core(const uint16_t* __restrict__ Ahi,
                                           const uint16_t* __restrict__ Alo,
                                           const uint16_t* __restrict__ Bhi,
                                           const uint16_t* __restrict__ Blo,
                                           int m0, float c[2][8][4],
                                           char* smem, int tid) {
    const int w = tid >> 5;
    const int lane = tid & 31;
    const uint32_t sb = (uint32_t)__cvta_generic_to_shared(smem);

    const int arow = (lane & 7) + ((lane >> 3) & 1) * 8;
    const int acol = (lane >> 4) * 16;                    // bytes
    const int brow = (lane & 7) + ((lane >> 4) & 1) * 8;
    const int bcol = ((lane >> 3) & 1) * 16;              // bytes

#pragma unroll
    for (int mg = 0; mg < 2; mg++)
#pragma unroll
        for (int nf = 0; nf < 8; nf++)
#pragma unroll
            for (int j = 0; j < 4; j++) c[mg][nf][j] = 0.f;

    auto stage = [&](int kc, int buf) {
        int k0 = kc * 32;
        uint32_t base = sb + buf * GBUF;
#pragma unroll
        for (int t = 0; t < 4; t++) {
            int i = tid + t * 128;
            int row = i >> 2, c16 = i & 3;
            size_t so = ((size_t)(m0 + row) * HIDDEN + k0) * 2 + c16 * 16;
            uint32_t d = base + row * 80 + c16 * 16;
            CP_ASYNC16(d + XH_OFF, (const char*)Ahi + so);
            CP_ASYNC16(d + XL_OFF, (const char*)Alo + so);
        }
#pragma unroll
        for (int t = 0; t < 2; t++) {
            int i = tid + t * 128;
            int row = i >> 2, c16 = i & 3;
            size_t so = ((size_t)row * HIDDEN + k0) * 2 + c16 * 16;
            uint32_t d = base + row * 80 + c16 * 16;
            CP_ASYNC16(d + WH_OFF, (const char*)Bhi + so);
            CP_ASYNC16(d + WL_OFF, (const char*)Blo + so);
        }
    };

    stage(0, 0);
    CP_COMMIT();

    for (int kc = 0; kc < NKCH; kc++) {
        if (kc + 1 < NKCH) {
            stage(kc + 1, (kc + 1) & 1);
            CP_COMMIT();
            CP_WAIT(1);
        } else {
            CP_WAIT(0);
        }
        __syncthreads();

        uint32_t base = sb + (kc & 1) * GBUF;
#pragma unroll
        for (int ks = 0; ks < 2; ks++) {
            uint32_t ah[2][4], al[2][4];
#pragma unroll
            for (int mg = 0; mg < 2; mg++) {
                uint32_t aaddr = base + XH_OFF + (w * 32 + mg * 16 + arow) * 80 + acol + ks * 32;
                LDSM_X4(ah[mg][0], ah[mg][1], ah[mg][2], ah[mg][3], aaddr);
                LDSM_X4(al[mg][0], al[mg][1], al[mg][2], al[mg][3], aaddr + (XL_OFF - XH_OFF));
            }
#pragma unroll
            for (int np = 0; np < 4; np++) {
                uint32_t baddr = base + WH_OFF + (np * 16 + brow) * 80 + bcol + ks * 32;
                uint32_t bh0, bh1, bh2, bh3, bl0, bl1, bl2, bl3;
                LDSM_X4(bh0, bh1, bh2, bh3, baddr);
                LDSM_X4(bl0, bl1, bl2, bl3, baddr + (WL_OFF - WH_OFF));
#pragma unroll
                for (int mg = 0; mg < 2; mg++) {
                    mma_bf16(c[mg][2 * np],     ah[mg], bh0, bh1);
                    mma_bf16(c[mg][2 * np],     ah[mg], bl0, bl1);
                    mma_bf16(c[mg][2 * np],     al[mg], bh0, bh1);
                    mma_bf16(c[mg][2 * np + 1], ah[mg], bh2, bh3);
                    mma_bf16(c[mg][2 * np + 1], ah[mg], bl2, bl3);
                    mma_bf16(c[mg][2 * np + 1], al[mg], bh2, bh3);
                }
            }
        }
        __syncthreads();
    }
}

// ---- fused QKV projection + bias + RoPE + transpose ----
__global__ __launch_bounds__(128) void gemm_qkv(const float* __restrict__ bq,
                                                const float* __restrict__ bk,
                                                const float* __restrict__ bv,
                                                const float2* __restrict__ rope,
                                                float* __restrict__ qo,
                                                float* __restrict__ ko,
                                                float* __restrict__ vt) {
    extern __shared__ char smem[];
    const int tid = threadIdx.x;
    const int w = tid >> 5;
    const int lane = tid & 31;
    const int lg = lane >> 2;
    const int lt = lane & 3;
    const int nt = blockIdx.x;
    const int m0 = blockIdx.y * 128;

    const uint16_t *Bhi, *Blo;
    const float* bias;
    if (nt < 14) {
        Bhi = (const uint16_t*)g_wqhi + (size_t)nt * 64 * HIDDEN;
        Blo = (const uint16_t*)g_wqlo + (size_t)nt * 64 * HIDDEN;
        bias = bq + nt * 64;
    } else if (nt < 16) {
        Bhi = (const uint16_t*)g_wkhi + (size_t)(nt - 14) * 64 * HIDDEN;
        Blo = (const uint16_t*)g_wklo + (size_t)(nt - 14) * 64 * HIDDEN;
        bias = bk + (nt - 14) * 64;
    } else {
        Bhi = (const uint16_t*)g_wvhi + (size_t)(nt - 16) * 64 * HIDDEN;
        Blo = (const uint16_t*)g_wvlo + (size_t)(nt - 16) * 64 * HIDDEN;
        bias = bv + (nt - 16) * 64;
    }

    float c[2][8][4];
    gemm3_core((const uint16_t*)g_xhi, (const uint16_t*)g_xlo, Bhi, Blo, m0, c, smem, tid);

#pragma unroll
    for (int mg = 0; mg < 2; mg++) {
#pragma unroll
        for (int rr = 0; rr < 2; rr++) {
            int row = m0 + w * 32 + mg * 16 + lg + rr * 8;   // token index
            int b = row >> 11;
            int s = row & (S - 1);
            if (nt < 16) {
                const bool isQ = (nt < 14);
                float* base = isQ
                    ? qo + (((size_t)b * NH + nt) * S + s) * HD
                    : ko + (((size_t)b * NKV + (nt - 14)) * S + s) * HD;
                const float sc = isQ ? ASCALE : 1.0f;
#pragma unroll
                for (int nf = 0; nf < 4; nf++) {
                    int d0 = nf * 8 + 2 * lt;
                    float2 t0 = rope[s * 32 + d0];
                    float2 t1 = rope[s * 32 + d0 + 1];
                    float x10 = c[mg][nf][rr * 2 + 0] + bias[d0];
                    float x11 = c[mg][nf][rr * 2 + 1] + bias[d0 + 1];
                    float x20 = c[mg][nf + 4][rr * 2 + 0] + bias[d0 + 32];
                    float x21 = c[mg][nf + 4][rr * 2 + 1] + bias[d0 + 33];
                    float y10 = (x10 * t0.x - x20 * t0.y) * sc;
                    float y11 = (x11 * t1.x - x21 * t1.y) * sc;
                    float y20 = (x20 * t0.x + x10 * t0.y) * sc;
                    float y21 = (x21 * t1.x + x11 * t1.y) * sc;
                    *reinterpret_cast<float2*>(base + d0) =
                        make_float2(__uint_as_float(f2tf32(y10)), __uint_as_float(f2tf32(y11)));
                    *reinterpret_cast<float2*>(base + d0 + 32) =
                        make_float2(__uint_as_float(f2tf32(y20)), __uint_as_float(f2tf32(y21)));
                }
            } else {
                // V transposed: [b][kv][d][s]
                float* base = vt + ((size_t)(b * NKV + (nt - 16)) * HD) * S + s;
#pragma unroll
                for (int nf = 0; nf < 8; nf++) {
                    int d0 = nf * 8 + 2 * lt;
                    base[(size_t)d0 * S] =
                        __uint_as_float(f2tf32(c[mg][nf][rr * 2 + 0] + bias[d0]));
                    base[(size_t)(d0 + 1) * S] =
                        __uint_as_float(f2tf32(c[mg][nf][rr * 2 + 1] + bias[d0 + 1]));
                }
            }
        }
    }
}

// ---- output projection: d_out = attn * Wo^T ----
__global__ __launch_bounds__(128) void gemm_out(float* __restrict__ C) {
    extern __shared__ char smem[];
    const int tid = threadIdx.x;
    const int w = tid >> 5;
    const int lane = tid & 31;
    const int lg = lane >> 2;
    const int lt = lane & 3;
    const int n0 = blockIdx.x * 64;
    const int m0 = blockIdx.y * 128;

    float c[2][8][4];
    gemm3_core((const uint16_t*)g_ahi, (const uint16_t*)g_alo,
               (const uint16_t*)g_wohi + (size_t)n0 * HIDDEN,
               (const uint16_t*)g_wolo + (size_t)n0 * HIDDEN,
               m0, c, smem, tid);

#pragma unroll
    for (int mg = 0; mg < 2; mg++) {
        const int row = m0 + w * 32 + mg * 16 + lg;
#pragma unroll
        for (int nf = 0; nf < 8; nf++) {
            int col = n0 + nf * 8 + 2 * lt;
            *reinterpret_cast<float2*>(&C[(size_t)row * HIDDEN + col]) =
                make_float2(c[mg][nf][0], c[mg][nf][1]);
            *reinterpret_cast<float2*>(&C[(size_t)(row + 8) * HIDDEN + col]) =
                make_float2(c[mg][nf][2], c[mg][nf][3]);
        }
    }
}

// -------- Flash attention: paired q-tiles (ILP), tf32 mma, double-buffered K/V --
// CTA = 128 thr handles q-tiles (2*pi, 2*pi+1) of the same head; K/V staged once.
// Per iter: QK_A, QK_B, softmax_A, PV_A, softmax_B, PV_B — scalar blocks sit
// between independent mma blocks of the SAME warp (ILP fills stalls).
#define AST 68
#define ATILE (64 * AST)                 // words per 64x64 tile (padded)
// layout: K0 | V0 | K1 | V1 | P_A | P_B
#define ATTN_SMEM (6 * ATILE * 4)        // 104448 B -> 2 CTAs/SM

__global__ __launch_bounds__(128, 2) void attn_kernel(const float* __restrict__ Q,
                                                      const float* __restrict__ K,
                                                      const float* __restrict__ V,   // [d][s]
                                                      uint32_t* __restrict__ Ohi,
                                                      uint32_t* __restrict__ Olo) {
    extern __shared__ uint32_t sm_u[];
    const uint32_t sbase = (uint32_t)__cvta_generic_to_shared(sm_u);
    const uint32_t psA = sbase + 4 * ATILE * 4;
    const uint32_t psB = sbase + 5 * ATILE * 4;

    const int pi = gridDim.x - 1 - blockIdx.x;   // heavy pairs launch first
    const int qtA = 2 * pi;
    const int qtB = 2 * pi + 1;
    const int h = blockIdx.y;
    const int b = blockIdx.z;
    const int kvh = h / NREP;
    const int tid = threadIdx.x;
    const int w = tid >> 5;                      // 4 warps
    const int lane = tid & 31;
    const int lg = lane >> 2;
    const int lt = lane & 3;

    const float* QbA = Q + (((size_t)b * NH + h) * S + (size_t)qtA * 64) * HD;
    const float* QbB = Q + (((size_t)b * NH + h) * S + (size_t)qtB * 64) * HD;
    const float* Kb = K + (((size_t)b * NKV + kvh) * S) * HD;
    const float* Vtb = V + ((size_t)(b * NKV + kvh) * HD) * S;

    // Q fragments for both tiles (pre-scaled, tf32-rounded at projection)
    uint32_t aqA[8][4], aqB[8][4];
    {
        const int r0 = w * 16 + lg;
#pragma unroll
        for (int ks = 0; ks < 8; ks++) {
            int c0 = ks * 8 + lt;
            aqA[ks][0] = __float_as_uint(QbA[(size_t)r0 * HD + c0]);
            aqA[ks][1] = __float_as_uint(QbA[(size_t)(r0 + 8) * HD + c0]);
            aqA[ks][2] = __float_as_uint(QbA[(size_t)r0 * HD + c0 + 4]);
            aqA[ks][3] = __float_as_uint(QbA[(size_t)(r0 + 8) * HD + c0 + 4]);
            aqB[ks][0] = __float_as_uint(QbB[(size_t)r0 * HD + c0]);
            aqB[ks][1] = __float_as_uint(QbB[(size_t)(r0 + 8) * HD + c0]);
            aqB[ks][2] = __float_as_uint(QbB[(size_t)r0 * HD + c0 + 4]);
            aqB[ks][3] = __float_as_uint(QbB[(size_t)(r0 + 8) * HD + c0 + 4]);
        }
    }

    const int k_row = ((lane >> 4) << 3) + (lane & 7);
    const int k_col = ((lane >> 3) & 1) << 2;            // words
    const int p_row = w * 16 + (lane & 15);
    const int p_col = (lane >> 4) << 2;

    float oA[8][4], oB[8][4], cA[8][4], cB[8][4];
#pragma unroll
    for (int n = 0; n < 8; n++)
#pragma unroll
        for (int j = 0; j < 4; j++) { oA[n][j] = 0.f; oB[n][j] = 0.f; }
    float mA0 = -1e30f, mA1 = -1e30f, lA0 = 0.f, lA1 = 0.f;   // l are LANE-PARTIAL
    float mB0 = -1e30f, mB1 = -1e30f, lB0 = 0.f, lB1 = 0.f;

    auto stage = [&](int kt, int buf) {
        uint32_t kb = sbase + (2 * buf) * ATILE * 4;
        uint32_t vb = sbase + (2 * buf + 1) * ATILE * 4;
#pragma unroll
        for (int i = tid; i < 2048; i += 128) {
            int isV = i >> 10;
            int idx = i & 1023;
            int r = idx >> 4;
            int cw = (idx & 15) * 4;
            if (isV) {
                CP_ASYNC16(vb + (uint32_t)((r * AST + cw) * 4),
                           Vtb + (size_t)r * S + (size_t)kt * 64 + cw);
            } else {
                CP_ASYNC16(kb + (uint32_t)((r * AST + cw) * 4),
                           Kb + ((size_t)kt * 64 + r) * HD + cw);
            }
        }
    };

    auto qk = [&](uint32_t (&aq)[8][4], float (&c)[8][4], int buf) {
        uint32_t kb = sbase + (2 * buf) * ATILE * 4;
#pragma unroll
        for (int n = 0; n < 8; n++)
#pragma unroll
            for (int j = 0; j < 4; j++) c[n][j] = 0.f;
#pragma unroll
        for (int ks = 0; ks < 8; ks++) {
#pragma unroll
            for (int jp = 0; jp < 4; jp++) {
                uint32_t kb0, kb1, kb2, kb3;
                uint32_t addr = kb + (uint32_t)(((jp * 16 + k_row) * AST + ks * 8 + k_col) * 4);
                LDSM_X4(kb0, kb1, kb2, kb3, addr);
                mma_tf32(c[2 * jp], aq[ks], kb0, kb1);
                mma_tf32(c[2 * jp + 1], aq[ks], kb2, kb3);
            }
        }
    };

    // softmax: mask (if diag), row-max reduce, exp2, store P, lane-partial l update
    auto softmax_t = [&](float (&c)[8][4], uint32_t psb,
                         float& m0r, float& m1r, float& l0r, float& l1r,
                         float (&o)[8][4], bool diag) {
        if (diag) {
            const int row0 = w * 16 + lg;
#pragma unroll
            for (int n = 0; n < 8; n++) {
                int col = n * 8 + 2 * lt;
                if (col > row0)         c[n][0] = -1e30f;
                if (col + 1 > row0)     c[n][1] = -1e30f;
                if (col > row0 + 8)     c[n][2] = -1e30f;
                if (col + 1 > row0 + 8) c[n][3] = -1e30f;
            }
        }
        float mx0 = -1e30f, mx1 = -1e30f;
#pragma unroll
        for (int n = 0; n < 8; n++) {
            mx0 = fmaxf(mx0, fmaxf(c[n][0], c[n][1]));
            mx1 = fmaxf(mx1, fmaxf(c[n][2], c[n][3]));
        }
        mx0 = fmaxf(mx0, __shfl_xor_sync(0xffffffffu, mx0, 1));
        mx0 = fmaxf(mx0, __shfl_xor_sync(0xffffffffu, mx0, 2));
        mx1 = fmaxf(mx1, __shfl_xor_sync(0xffffffffu, mx1, 1));
        mx1 = fmaxf(mx1, __shfl_xor_sync(0xffffffffu, mx1, 2));

        float mn0 = fmaxf(m0r, mx0);
        float mn1 = fmaxf(m1r, mx1);
        float corr0 = exp2f(m0r - mn0);
        float corr1 = exp2f(m1r - mn1);

        float sum0 = 0.f, sum1 = 0.f;
        {
            const int r0 = w * 16 + lg;
            uint32_t p0base = psb + (uint32_t)((r0 * AST + 2 * lt) * 4);
            uint32_t p1base = psb + (uint32_t)(((r0 + 8) * AST + 2 * lt) * 4);
#pragma unroll
            for (int n = 0; n < 8; n++) {
                float p00 = exp2f(c[n][0] - mn0);
                float p01 = exp2f(c[n][1] - mn0);
                float p10 = exp2f(c[n][2] - mn1);
                float p11 = exp2f(c[n][3] - mn1);
                sum0 += p00 + p01;
                sum1 += p10 + p11;
                uint2 v0 = make_uint2(f2tf32(p00), f2tf32(p01));
                uint2 v1 = make_uint2(f2tf32(p10), f2tf32(p11));
                asm volatile("st.shared.v2.b32 [%0], {%1,%2};" :: "r"(p0base + n * 32), "r"(v0.x), "r"(v0.y));
                asm volatile("st.shared.v2.b32 [%0], {%1,%2};" :: "r"(p1base + n * 32), "r"(v1.x), "r"(v1.y));
            }
        }
        // lane-partial l (cross-lane reduce deferred to epilogue)
        l0r = l0r * corr0 + sum0;
        l1r = l1r * corr1 + sum1;
        m0r = mn0;
        m1r = mn1;
#pragma unroll
        for (int n = 0; n < 8; n++) {
            o[n][0] *= corr0;
            o[n][1] *= corr0;
            o[n][2] *= corr1;
            o[n][3] *= corr1;
        }
        __syncwarp();
    };

    auto pv = [&](uint32_t psb, float (&o)[8][4], int buf) {
        uint32_t vb = sbase + (2 * buf + 1) * ATILE * 4;
#pragma unroll
        for (int ks = 0; ks < 8; ks++) {
            uint32_t pa[4];
            uint32_t paddr = psb + (uint32_t)((p_row * AST + ks * 8 + p_col) * 4);
            LDSM_X4(pa[0], pa[1], pa[2], pa[3], paddr);
#pragma unroll
            for (int jp = 0; jp < 4; jp++) {
                uint32_t v0, v1, v2, v3;
                uint32_t addr = vb + (uint32_t)(((jp * 16 + k_row) * AST + ks * 8 + k_col) * 4);
                LDSM_X4(v0, v1, v2, v3, addr);
                mma_tf32(o[2 * jp], pa, v0, v1);
                mma_tf32(o[2 * jp + 1], pa, v2, v3);
            }
        }
    };

    // prologue
    stage(0, 0);
    CP_COMMIT();

    // joint loop: both tiles active for kt in [0, qtA]; stage always reaches qtB
    for (int kt = 0; kt <= qtA; kt++) {
        const int cur = kt & 1;
        stage(kt + 1, cur ^ 1);          // kt+1 <= qtB always holds here
        CP_COMMIT();
        CP_WAIT(1);
        __syncthreads();

        qk(aqA, cA, cur);
        qk(aqB, cB, cur);

        softmax_t(cA, psA, mA0, mA1, lA0, lA1, oA, kt == qtA);
        pv(psA, oA, cur);

        softmax_t(cB, psB, mB0, mB1, lB0, lB1, oB, false);
        pv(psB, oB, cur);

        __syncthreads();
    }

    // solo iteration for tile B: kt = qtB (diagonal)
    {
        const int cur = qtB & 1;
        CP_WAIT(0);
        __syncthreads();
        qk(aqB, cB, cur);
        softmax_t(cB, psB, mB0, mB1, lB0, lB1, oB, true);
        pv(psB, oB, cur);
    }

    // final cross-lane l reduction
    lA0 += __shfl_xor_sync(0xffffffffu, lA0, 1);
    lA0 += __shfl_xor_sync(0xffffffffu, lA0, 2);
    lA1 += __shfl_xor_sync(0xffffffffu, lA1, 1);
    lA1 += __shfl_xor_sync(0xffffffffu, lA1, 2);
    lB0 += __shfl_xor_sync(0xffffffffu, lB0, 1);
    lB0 += __shfl_xor_sync(0xffffffffu, lB0, 2);
    lB1 += __shfl_xor_sync(0xffffffffu, lB1, 1);
    lB1 += __shfl_xor_sync(0xffffffffu, lB1, 2);

    // ---- write normalized outputs as bf16 hi/lo ----
    auto write_out = [&](float (&o)[8][4], float l0, float l1, int qt) {
        float inv0 = 1.f / l0;
        float inv1 = 1.f / l1;
        const int r0 = qt * 64 + w * 16 + lg;
        size_t base0 = ((size_t)b * S + r0) * HIDDEN + h * HD + 2 * lt;
        size_t base1 = ((size_t)b * S + r0 + 8) * HIDDEN + h * HD + 2 * lt;
#pragma unroll
        for (int n = 0; n < 8; n++) {
            uint32_t hi, lo;
            split2(o[n][0] * inv0, o[n][1] * inv0, hi, lo);
            Ohi[(base0 + n * 8) >> 1] = hi;
            Olo[(base0 + n * 8) >> 1] = lo;
            split2(o[n][2] * inv1, o[n][3] * inv1, hi, lo);
            Ohi[(base1 + n * 8) >> 1] = hi;
            Olo[(base1 + n * 8) >> 1] = lo;
        }
    };
    write_out(oA, lA0, lA1, qtA);
    write_out(oB, lB0, lB1, qtB);
}

// ---------------- launch ----------------
extern "C" void kernel_launch(void* const* d_in, const int* in_sizes, int n_in,
                              void* d_out, int out_size) {
    const float* hs = (const float*)d_in[0];
    const float* Wq = (const float*)d_in[2];
    const float* bq = (const float*)d_in[3];
    const float* Wk = (const float*)d_in[4];
    const float* bk = (const float*)d_in[5];
    const float* Wv = (const float*)d_in[6];
    const float* bv = (const float*)d_in[7];
    const float* Wo = (const float*)d_in[8];
    float* out = (float*)d_out;

    float *q, *k, *vt;
    float2* rope;
    uint2 *ahi, *alo;
    cudaGetSymbolAddress((void**)&q, g_q);
    cudaGetSymbolAddress((void**)&k, g_k);
    cudaGetSymbolAddress((void**)&vt, g_vt);
    cudaGetSymbolAddress((void**)&rope, g_rope);
    cudaGetSymbolAddress((void**)&ahi, g_ahi);
    cudaGetSymbolAddress((void**)&alo, g_alo);

    static bool attr_set = false;
    if (!attr_set) {
        cudaFuncSetAttribute(attn_kernel, cudaFuncAttributeMaxDynamicSharedMemorySize, ATTN_SMEM);
        cudaFuncSetAttribute(gemm_qkv, cudaFuncAttributeMaxDynamicSharedMemorySize, GEMM_SMEM);
        cudaFuncSetAttribute(gemm_out, cudaFuncAttributeMaxDynamicSharedMemorySize, GEMM_SMEM);
        attr_set = true;
    }

    build_rope<<<(S * 32) / 256, 256>>>(rope);
    conv_split<<<(TOT4 + 255) / 256, 256>>>((const float4*)hs, (const float4*)Wq,
                                            (const float4*)Wk, (const float4*)Wv,
                                            (const float4*)Wo);

    gemm_qkv<<<dim3(18, MTOK / 128), 128, GEMM_SMEM>>>(bq, bk, bv, rope, q, k, vt);

    // paired q-tiles: grid.x = S/128 pairs
    attn_kernel<<<dim3(S / 128, NH, B), 128, ATTN_SMEM>>>(q, k, vt,
                                                          (uint32_t*)ahi, (uint32_t*)alo);

    gemm_out<<<dim3(HIDDEN / 64, MTOK / 128), 128, GEMM_SMEM>>>(out);
}